// round 16
// baseline (speedup 1.0000x reference)
#include <cuda_runtime.h>
#include <cstdint>
#include <cstddef>

#define BATCH 4
#define CH    256
#define QVCH  512
#define NPIX  9216   // 96*96
#define MPIX  256    // 16*16
#define HEADS 4
#define DHEAD 64
#define NBH   (BATCH*HEADS)
#define NCHUNK 18               // 9216 / 512
#define SCALE 0.125f

#define AP 20    // conv A pad
#define BP 136   // conv B pad

// ---------------- scratch ----------------
__device__ float g_fqv[BATCH*QVCH*NPIX];
__device__ float g_mqv[BATCH*QVCH*MPIX];
__device__ float g_feato[BATCH*CH*NPIX];
__device__ float g_mapo[BATCH*CH*MPIX];
__device__ float g_dpart[(size_t)NCHUNK*NBH*64*256];
__device__ float g_cspart[NCHUNK*NBH*256];

// ---------------- tf32 helpers ----------------
__device__ __forceinline__ float to_tf32(float x) {
    float r; asm("cvt.rna.tf32.f32 %0, %1;" : "=f"(r) : "f"(x)); return r;
}
__device__ __forceinline__ void mma8(float* d, const uint32_t* a, const uint32_t* b) {
    asm volatile("mma.sync.aligned.m16n8k8.row.col.f32.tf32.tf32.f32 "
        "{%0,%1,%2,%3}, {%4,%5,%6,%7}, {%8,%9}, {%0,%1,%2,%3};\n"
        : "+f"(d[0]), "+f"(d[1]), "+f"(d[2]), "+f"(d[3])
        : "r"(a[0]), "r"(a[1]), "r"(a[2]), "r"(a[3]), "r"(b[0]), "r"(b[1]));
}
#define U(x) __float_as_uint(x)

// profiling position marker: keeps fused_attn as the 4th launch (the one ncu captures)
__global__ void prof_marker() {}

// =================== tf32 tensor-core 1x1-conv GEMM (R14 proven) ===================
__global__ void __launch_bounds__(256, 2)
conv_tf32(const float* __restrict__ Wm, const float* __restrict__ X,
          float* __restrict__ Y, int C, int Npix, int O) {
    __shared__ float As[128*AP];
    __shared__ float Bs[16*BP];
    int b = blockIdx.z;
    const float* Xb = X + (size_t)b*C*Npix;
    float* Yb = Y + (size_t)b*O*Npix;
    int o0 = blockIdx.y*128, n0 = blockIdx.x*128;
    int tid = threadIdx.x;
    int lane = tid & 31, w = tid >> 5;
    int g = lane >> 2, tg = lane & 3;
    int wm = (w >> 2) * 64, wn = (w & 3) * 32;

    int oA = tid >> 2, cqA = (tid & 3) << 2;
    int cB = tid >> 5, nB = (tid & 31) << 2;
    const float* WpA = Wm + (size_t)(o0 + oA)*C + cqA;
    const float* XpB = Xb + (size_t)cB*Npix + n0 + nB;

    float acc[4][4][4] = {};
    float4 a0w = *(const float4*)WpA;
    float4 a1w = *(const float4*)(WpA + (size_t)64*C);
    float4 b0w = *(const float4*)XpB;
    float4 b1w = *(const float4*)(XpB + (size_t)8*Npix);

    for (int k0 = 0; k0 < C; k0 += 16) {
        float4 t;
        t.x=to_tf32(a0w.x); t.y=to_tf32(a0w.y); t.z=to_tf32(a0w.z); t.w=to_tf32(a0w.w);
        *(float4*)&As[oA*AP + cqA] = t;
        t.x=to_tf32(a1w.x); t.y=to_tf32(a1w.y); t.z=to_tf32(a1w.z); t.w=to_tf32(a1w.w);
        *(float4*)&As[(oA+64)*AP + cqA] = t;
        t.x=to_tf32(b0w.x); t.y=to_tf32(b0w.y); t.z=to_tf32(b0w.z); t.w=to_tf32(b0w.w);
        *(float4*)&Bs[cB*BP + nB] = t;
        t.x=to_tf32(b1w.x); t.y=to_tf32(b1w.y); t.z=to_tf32(b1w.z); t.w=to_tf32(b1w.w);
        *(float4*)&Bs[(cB+8)*BP + nB] = t;
        __syncthreads();
        if (k0 + 16 < C) {
            a0w = *(const float4*)(WpA + k0 + 16);
            a1w = *(const float4*)(WpA + (size_t)64*C + k0 + 16);
            b0w = *(const float4*)(XpB + (size_t)(k0+16)*Npix);
            b1w = *(const float4*)(XpB + (size_t)(k0+24)*Npix);
        }
        #pragma unroll
        for (int kk = 0; kk < 2; kk++) {
            int kb = kk*8;
            uint32_t a[4][4], bb[4][2];
            #pragma unroll
            for (int mt = 0; mt < 4; mt++) {
                int m = wm + mt*16 + g;
                a[mt][0] = U(As[m*AP + kb + tg]);
                a[mt][1] = U(As[(m+8)*AP + kb + tg]);
                a[mt][2] = U(As[m*AP + kb + tg + 4]);
                a[mt][3] = U(As[(m+8)*AP + kb + tg + 4]);
            }
            #pragma unroll
            for (int nt = 0; nt < 4; nt++) {
                int n = wn + nt*8 + g;
                bb[nt][0] = U(Bs[(kb+tg)*BP + n]);
                bb[nt][1] = U(Bs[(kb+tg+4)*BP + n]);
            }
            #pragma unroll
            for (int mt = 0; mt < 4; mt++)
                #pragma unroll
                for (int nt = 0; nt < 4; nt++)
                    mma8(acc[mt][nt], a[mt], bb[nt]);
        }
        __syncthreads();
    }
    #pragma unroll
    for (int mt = 0; mt < 4; mt++) {
        int orow = o0 + wm + mt*16 + g;
        #pragma unroll
        for (int nt = 0; nt < 4; nt++) {
            int nc = n0 + wn + nt*8 + 2*tg;
            *(float2*)&Yb[(size_t)orow*Npix + nc] = make_float2(acc[mt][nt][0], acc[mt][nt][1]);
            *(float2*)&Yb[(size_t)(orow+8)*Npix + nc] = make_float2(acc[mt][nt][2], acc[mt][nt][3]);
        }
    }
}

// =================== small 64x64 conv (MPIX side, fp32) ===================
__global__ void conv1x1_small(const float* __restrict__ Wm,
                              const float* __restrict__ X,
                              float* __restrict__ Y,
                              int C, int Npix, int O) {
    __shared__ float As[16][65];
    __shared__ float Bs[16][64];
    int b = blockIdx.z;
    const float* Xb = X + (size_t)b * C * Npix;
    float* Yb = Y + (size_t)b * O * Npix;
    int o0 = blockIdx.y * 64, n0 = blockIdx.x * 64;
    int tid = threadIdx.x;
    int tx = tid & 15, ty = tid >> 4;
    float acc[4][4] = {};
    for (int k0 = 0; k0 < C; k0 += 16) {
        #pragma unroll
        for (int r = 0; r < 4; r++) {
            int idx = tid + r * 256;
            int c = idx & 15, o = idx >> 4;
            As[c][o] = Wm[(size_t)(o0 + o) * C + k0 + c];
        }
        #pragma unroll
        for (int r = 0; r < 4; r++) {
            int idx = tid + r * 256;
            int n = idx & 63, c = idx >> 6;
            Bs[c][n] = Xb[(size_t)(k0 + c) * Npix + n0 + n];
        }
        __syncthreads();
        #pragma unroll
        for (int k = 0; k < 16; k++) {
            float a[4], bb[4];
            #pragma unroll
            for (int r = 0; r < 4; r++) a[r] = As[k][ty * 4 + r];
            #pragma unroll
            for (int c2 = 0; c2 < 4; c2++) bb[c2] = Bs[k][tx * 4 + c2];
            #pragma unroll
            for (int r = 0; r < 4; r++)
                #pragma unroll
                for (int c2 = 0; c2 < 4; c2++) acc[r][c2] += a[r] * bb[c2];
        }
        __syncthreads();
    }
    #pragma unroll
    for (int r = 0; r < 4; r++)
        #pragma unroll
        for (int c2 = 0; c2 < 4; c2++)
            Yb[(size_t)(o0 + ty * 4 + r) * Npix + n0 + tx * 4 + c2] = acc[r][c2];
}

// =================== FUSED attention: 512 threads (16 warps), same smem ===================
// warp grids (4x4): logits 16i x 64j, feato 16i x 16d, mapo 16d x 64j
// smem (floats): Ks@0 [64][264], Vs@16896 [64][264], Ps@33792 [64][260],
//   QF@50432 [64][72] (reused [64][68]), rsw@55040 [64][4], csw@55296 [4][256],
//   csr@56320 [256]  -> total 56576 floats = 226304 B
__global__ void __launch_bounds__(512)
fused_attn(const float* __restrict__ fqv, const float* __restrict__ mqv,
           float* __restrict__ feato, float* __restrict__ dpart,
           float* __restrict__ cspart) {
    extern __shared__ float sm[];
    float* Ks  = sm;
    float* Vs  = sm + 16896;
    float* Ps  = sm + 33792;
    float* QF  = sm + 50432;
    float* rsw = sm + 55040;
    float* csw = sm + 55296;
    float* csr = sm + 56320;

    int chunk = blockIdx.x, bh = blockIdx.y;
    int b = bh >> 2, h = bh & 3;
    const float* qb  = fqv + (size_t)b * QVCH * NPIX;
    const float* fvb = qb + (size_t)CH * NPIX;
    const float* kbg = mqv + (size_t)b * QVCH * MPIX;
    const float* vbg = kbg + (size_t)CH * MPIX;

    int tid = threadIdx.x, lane = tid & 31, w = tid >> 5;
    int g = lane >> 2, tg = lane & 3;
    int wi4 = (w >> 2), wj4 = (w & 3);        // 4x4 warp grid
    int wli = wi4 * 16, wlj = wj4 * 64;       // logits tile
    int wfi = wli,      wfd = wj4 * 16;       // feato tile
    int wmd = wi4 * 16, wmj = wj4 * 64;       // mapo tile

    // CTA init: K scaled+tf32 once; V tf32
    #pragma unroll
    for (int it = 0; it < 8; it++) {
        int q4 = tid + it * 512;
        int d = q4 >> 6, j4 = (q4 & 63) << 2;
        float4 kv = *(const float4*)(kbg + (size_t)((d << 2) + h) * MPIX + j4);
        kv.x = to_tf32(kv.x * SCALE); kv.y = to_tf32(kv.y * SCALE);
        kv.z = to_tf32(kv.z * SCALE); kv.w = to_tf32(kv.w * SCALE);
        *(float4*)&Ks[d * 264 + j4] = kv;
        float4 vv = *(const float4*)(vbg + (size_t)((d << 2) + h) * MPIX + j4);
        vv.x = to_tf32(vv.x); vv.y = to_tf32(vv.y); vv.z = to_tf32(vv.z); vv.w = to_tf32(vv.w);
        *(float4*)&Vs[d * 264 + j4] = vv;
    }
    if (tid < 256) csr[tid] = 0.f;

    float acc_mo[8][4] = {};   // persistent 16d x 64j partial

    for (int blk = 0; blk < 8; blk++) {
        int gi0 = chunk * 512 + blk * 64;
        __syncthreads();
        // Q staged pre-truncated to tf32
        #pragma unroll
        for (int it = 0; it < 2; it++) {
            int q4 = tid + it * 512;
            int d = q4 >> 4, i4 = (q4 & 15) << 2;
            float4 qv = *(const float4*)(qb + (size_t)((d << 2) + h) * NPIX + gi0 + i4);
            qv.x = to_tf32(qv.x); qv.y = to_tf32(qv.y);
            qv.z = to_tf32(qv.z); qv.w = to_tf32(qv.w);
            *(float4*)&QF[d * 72 + i4] = qv;
        }
        __syncthreads();

        // ---- logits 1xTF32: warp 16i x 64j ----
        float accs[8][4] = {};
        #pragma unroll
        for (int kb8 = 0; kb8 < 64; kb8 += 8) {
            uint32_t abig[4];
            abig[0] = U(QF[(kb8 + tg) * 72 + wli + g]);
            abig[1] = U(QF[(kb8 + tg) * 72 + wli + g + 8]);
            abig[2] = U(QF[(kb8 + tg + 4) * 72 + wli + g]);
            abig[3] = U(QF[(kb8 + tg + 4) * 72 + wli + g + 8]);
            #pragma unroll
            for (int nt = 0; nt < 8; nt++) {
                int n = wlj + nt * 8 + g;
                uint32_t bb[2] = {U(Ks[(kb8 + tg) * 264 + n]), U(Ks[(kb8 + tg + 4) * 264 + n])};
                mma8(accs[nt], abig, bb);
            }
        }

        // ---- exp + row partials (over 64 j) + col partials (over 16 i) ----
        float rs0 = 0.f, rs1 = 0.f;
        float cs0[8], cs1[8];
        #pragma unroll
        for (int nt = 0; nt < 8; nt++) {
            accs[nt][0] = __expf(accs[nt][0]);
            accs[nt][1] = __expf(accs[nt][1]);
            accs[nt][2] = __expf(accs[nt][2]);
            accs[nt][3] = __expf(accs[nt][3]);
            rs0 += accs[nt][0] + accs[nt][1];
            rs1 += accs[nt][2] + accs[nt][3];
            cs0[nt] = accs[nt][0] + accs[nt][2];
            cs1[nt] = accs[nt][1] + accs[nt][3];
        }
        #pragma unroll
        for (int off = 1; off <= 2; off <<= 1) {
            rs0 += __shfl_xor_sync(0xffffffffu, rs0, off);
            rs1 += __shfl_xor_sync(0xffffffffu, rs1, off);
        }
        if (tg == 0) {
            rsw[(wli + g) * 4 + wj4] = rs0;
            rsw[(wli + g + 8) * 4 + wj4] = rs1;
        }
        #pragma unroll
        for (int off = 4; off <= 16; off <<= 1) {
            #pragma unroll
            for (int nt = 0; nt < 8; nt++) {
                cs0[nt] += __shfl_xor_sync(0xffffffffu, cs0[nt], off);
                cs1[nt] += __shfl_xor_sync(0xffffffffu, cs1[nt], off);
            }
        }
        #pragma unroll
        for (int nt = 0; nt < 8; nt++) {
            if (g == nt) {
                csw[wi4 * 256 + wlj + nt * 8 + tg * 2]     = cs0[nt];
                csw[wi4 * 256 + wlj + nt * 8 + tg * 2 + 1] = cs1[nt];
            }
        }
        __syncthreads();

        if (tid < 256)
            csr[tid] += csw[tid] + csw[256 + tid] + csw[512 + tid] + csw[768 + tid];
        float inv0 = 1.f / (rsw[(wli + g) * 4] + rsw[(wli + g) * 4 + 1] +
                            rsw[(wli + g) * 4 + 2] + rsw[(wli + g) * 4 + 3]);
        float inv1 = 1.f / (rsw[(wli + g + 8) * 4] + rsw[(wli + g + 8) * 4 + 1] +
                            rsw[(wli + g + 8) * 4 + 2] + rsw[(wli + g + 8) * 4 + 3]);
        #pragma unroll
        for (int nt = 0; nt < 8; nt++) {
            int col = wlj + nt * 8 + 2 * tg;
            Ps[(wli + g) * 260 + col]         = to_tf32(accs[nt][0] * inv0);
            Ps[(wli + g) * 260 + col + 1]     = to_tf32(accs[nt][1] * inv0);
            Ps[(wli + g + 8) * 260 + col]     = to_tf32(accs[nt][2] * inv1);
            Ps[(wli + g + 8) * 260 + col + 1] = to_tf32(accs[nt][3] * inv1);
        }
        __syncthreads();

        // ---- feato: O = P @ V^T (warp 16i x 16d, K=256) ----
        float acco[2][4] = {};
        #pragma unroll 4
        for (int k0 = 0; k0 < 256; k0 += 8) {
            uint32_t a[4];
            a[0] = U(Ps[(wfi + g) * 260 + k0 + tg]);
            a[1] = U(Ps[(wfi + g + 8) * 260 + k0 + tg]);
            a[2] = U(Ps[(wfi + g) * 260 + k0 + tg + 4]);
            a[3] = U(Ps[(wfi + g + 8) * 260 + k0 + tg + 4]);
            #pragma unroll
            for (int nt = 0; nt < 2; nt++) {
                int n = wfd + nt * 8 + g;
                uint32_t bb[2] = {U(Vs[n * 264 + k0 + tg]), U(Vs[n * 264 + k0 + tg + 4])};
                mma8(acco[nt], a, bb);
            }
        }
        // ---- fv * rowsum -> QF as A-tile [d 64][i 68] tf32 ----
        #pragma unroll
        for (int it = 0; it < 8; it++) {
            int idx = tid + it * 512;
            int i = idx & 63, d = idx >> 6;
            float rsv = rsw[i * 4] + rsw[i * 4 + 1] + rsw[i * 4 + 2] + rsw[i * 4 + 3];
            QF[d * 68 + i] = to_tf32(fvb[(size_t)((d << 2) + h) * NPIX + gi0 + i] * rsv);
        }
        __syncthreads();

        // ---- mapo: D += fv' @ P (warp 16d x 64j, K=64) ----
        #pragma unroll
        for (int kb = 0; kb < 64; kb += 8) {
            uint32_t am[4];
            am[0] = U(QF[(wmd + g) * 68 + kb + tg]);
            am[1] = U(QF[(wmd + g + 8) * 68 + kb + tg]);
            am[2] = U(QF[(wmd + g) * 68 + kb + tg + 4]);
            am[3] = U(QF[(wmd + g + 8) * 68 + kb + tg + 4]);
            #pragma unroll
            for (int nt = 0; nt < 8; nt++) {
                int n = wmj + nt * 8 + g;
                uint32_t bb[2] = {U(Ps[(kb + tg) * 260 + n]), U(Ps[(kb + tg + 4) * 260 + n])};
                mma8(acc_mo[nt], am, bb);
            }
        }
        __syncthreads();

        // ---- O staging (reuse Ps as [i 64][d 65]) + coalesced store ----
        float* OS = Ps;
        #pragma unroll
        for (int nt = 0; nt < 2; nt++) {
            int dc = wfd + nt * 8 + 2 * tg;
            OS[(wfi + g) * 65 + dc]         = acco[nt][0];
            OS[(wfi + g) * 65 + dc + 1]     = acco[nt][1];
            OS[(wfi + g + 8) * 65 + dc]     = acco[nt][2];
            OS[(wfi + g + 8) * 65 + dc + 1] = acco[nt][3];
        }
        __syncthreads();
        float* fb = feato + (size_t)b * CH * NPIX;
        #pragma unroll
        for (int it = 0; it < 8; it++) {
            int idx = tid + it * 512;
            int i = idx & 63, d = idx >> 6;
            fb[(size_t)((d << 2) + h) * NPIX + gi0 + i] = OS[i * 65 + d];
        }
    }

    // ---- CTA epilogue: D partial [d 64][j 260] in Ps, write + cs ----
    __syncthreads();
    float* St = Ps;
    #pragma unroll
    for (int nt = 0; nt < 8; nt++) {
        int jc = wmj + nt * 8 + 2 * tg;
        St[(wmd + g) * 260 + jc]           = acc_mo[nt][0];
        St[(wmd + g) * 260 + jc + 1]       = acc_mo[nt][1];
        St[(wmd + g + 8) * 260 + jc]       = acc_mo[nt][2];
        St[(wmd + g + 8) * 260 + jc + 1]   = acc_mo[nt][3];
    }
    __syncthreads();
    float* dp = dpart + ((size_t)chunk * NBH + bh) * (64 * 256);
    #pragma unroll
    for (int it = 0; it < 8; it++) {
        int q4 = tid + it * 512;
        int d = q4 >> 6, j4 = (q4 & 63) << 2;
        *(float4*)&dp[d * 256 + j4] = make_float4(St[d * 260 + j4], St[d * 260 + j4 + 1],
                                                  St[d * 260 + j4 + 2], St[d * 260 + j4 + 3]);
    }
    if (tid < 256)
        cspart[((size_t)chunk * NBH + bh) * 256 + tid] = csr[tid];
}

// =================== mapo finalize (1024 blocks) ===================
__global__ void mapo_finalize(const float* __restrict__ dpart,
                              const float* __restrict__ cspart,
                              float* __restrict__ mapo) {
    int bh = blockIdx.x; int b = bh >> 2, h = bh & 3;
    int d = blockIdx.y;
    int j = threadIdx.x;
    float s = 0.f;
    #pragma unroll
    for (int ch = 0; ch < NCHUNK; ch++)
        s += cspart[((size_t)ch * NBH + bh) * 256 + j];
    float acc = 0.f;
    #pragma unroll
    for (int ch = 0; ch < NCHUNK; ch++)
        acc += dpart[((size_t)ch * NBH + bh) * (64 * 256) + d * 256 + j];
    mapo[(size_t)b * CH * MPIX + (size_t)((d << 2) + h) * MPIX + j] = acc / s;
}

// ---------------- host launch ----------------
extern "C" void kernel_launch(void* const* d_in, const int* in_sizes, int n_in,
                              void* d_out, int out_size) {
    const float* feat = (const float*)d_in[0];
    const float* smap = (const float*)d_in[1];
    const float* Wfqv = (const float*)d_in[2];
    const float* Wmqv = (const float*)d_in[3];
    const float* Wfo  = (const float*)d_in[4];
    const float* Wmo  = (const float*)d_in[5];
    float* out = (float*)d_out;
    float* feat_out = out;
    float* map_out  = out + (size_t)BATCH * CH * NPIX;

    float *p_fqv, *p_mqv, *p_feato, *p_mapo, *p_dpart, *p_cspart;
    cudaGetSymbolAddress((void**)&p_fqv, g_fqv);
    cudaGetSymbolAddress((void**)&p_mqv, g_mqv);
    cudaGetSymbolAddress((void**)&p_feato, g_feato);
    cudaGetSymbolAddress((void**)&p_mapo, g_mapo);
    cudaGetSymbolAddress((void**)&p_dpart, g_dpart);
    cudaGetSymbolAddress((void**)&p_cspart, g_cspart);

    const int fused_smem = 56576 * 4;   // 226304 B
    cudaFuncSetAttribute(fused_attn, cudaFuncAttributeMaxDynamicSharedMemorySize, fused_smem);

    // 1) QV projections
    conv_tf32<<<dim3(NPIX / 128, QVCH / 128, BATCH), 256>>>(Wfqv, feat, p_fqv, CH, NPIX, QVCH);
    conv1x1_small<<<dim3(MPIX / 64, QVCH / 64, BATCH), 256>>>(Wmqv, smap, p_mqv, CH, MPIX, QVCH);

    // marker so fused_attn is the 4th launch (profiled by ncu)
    prof_marker<<<1, 32>>>();

    // 2) fused attention (512 threads, 16 warps)
    fused_attn<<<dim3(NCHUNK, NBH), 512, fused_smem>>>(p_fqv, p_mqv, p_feato, p_dpart, p_cspart);

    // 3) map_o finalize
    mapo_finalize<<<dim3(NBH, 64), 256>>>(p_dpart, p_cspart, p_mapo);

    // 4) output projections
    conv_tf32<<<dim3(NPIX / 128, CH / 128, BATCH), 256>>>(Wfo, p_feato, feat_out, CH, NPIX, CH);
    conv1x1_small<<<dim3(MPIX / 64, CH / 64, BATCH), 256>>>(Wmo, p_mapo, map_out, CH, MPIX, CH);
}

// round 17
// speedup vs baseline: 1.0494x; 1.0494x over previous
#include <cuda_runtime.h>
#include <cstdint>
#include <cstddef>

#define BATCH 4
#define CH    256
#define QVCH  512
#define NPIX  9216   // 96*96
#define MPIX  256    // 16*16
#define HEADS 4
#define DHEAD 64
#define NBH   (BATCH*HEADS)
#define NCHUNK 18               // 9216 / 512
#define SCALE 0.125f

#define AP 20    // conv A pad
#define BP 136   // conv B pad

// ---------------- scratch ----------------
__device__ float g_fqv[BATCH*QVCH*NPIX];
__device__ float g_mqv[BATCH*QVCH*MPIX];
__device__ float g_feato[BATCH*CH*NPIX];
__device__ float g_mapo[BATCH*CH*MPIX];
__device__ float g_dpart[(size_t)NCHUNK*NBH*64*256];
__device__ float g_cspart[NCHUNK*NBH*256];

// ---------------- tf32 helpers ----------------
__device__ __forceinline__ float to_tf32(float x) {
    float r; asm("cvt.rna.tf32.f32 %0, %1;" : "=f"(r) : "f"(x)); return r;
}
__device__ __forceinline__ void mma8(float* d, const uint32_t* a, const uint32_t* b) {
    asm volatile("mma.sync.aligned.m16n8k8.row.col.f32.tf32.tf32.f32 "
        "{%0,%1,%2,%3}, {%4,%5,%6,%7}, {%8,%9}, {%0,%1,%2,%3};\n"
        : "+f"(d[0]), "+f"(d[1]), "+f"(d[2]), "+f"(d[3])
        : "r"(a[0]), "r"(a[1]), "r"(a[2]), "r"(a[3]), "r"(b[0]), "r"(b[1]));
}
#define U(x) __float_as_uint(x)

// profiling position marker: keeps fused_attn as the 4th launch (the one ncu captures)
__global__ void prof_marker() {}

// =================== tf32 tensor-core 1x1-conv GEMM (R14 proven) ===================
__global__ void __launch_bounds__(256, 2)
conv_tf32(const float* __restrict__ Wm, const float* __restrict__ X,
          float* __restrict__ Y, int C, int Npix, int O) {
    __shared__ float As[128*AP];
    __shared__ float Bs[16*BP];
    int b = blockIdx.z;
    const float* Xb = X + (size_t)b*C*Npix;
    float* Yb = Y + (size_t)b*O*Npix;
    int o0 = blockIdx.y*128, n0 = blockIdx.x*128;
    int tid = threadIdx.x;
    int lane = tid & 31, w = tid >> 5;
    int g = lane >> 2, tg = lane & 3;
    int wm = (w >> 2) * 64, wn = (w & 3) * 32;

    int oA = tid >> 2, cqA = (tid & 3) << 2;
    int cB = tid >> 5, nB = (tid & 31) << 2;
    const float* WpA = Wm + (size_t)(o0 + oA)*C + cqA;
    const float* XpB = Xb + (size_t)cB*Npix + n0 + nB;

    float acc[4][4][4] = {};
    float4 a0w = *(const float4*)WpA;
    float4 a1w = *(const float4*)(WpA + (size_t)64*C);
    float4 b0w = *(const float4*)XpB;
    float4 b1w = *(const float4*)(XpB + (size_t)8*Npix);

    for (int k0 = 0; k0 < C; k0 += 16) {
        float4 t;
        t.x=to_tf32(a0w.x); t.y=to_tf32(a0w.y); t.z=to_tf32(a0w.z); t.w=to_tf32(a0w.w);
        *(float4*)&As[oA*AP + cqA] = t;
        t.x=to_tf32(a1w.x); t.y=to_tf32(a1w.y); t.z=to_tf32(a1w.z); t.w=to_tf32(a1w.w);
        *(float4*)&As[(oA+64)*AP + cqA] = t;
        t.x=to_tf32(b0w.x); t.y=to_tf32(b0w.y); t.z=to_tf32(b0w.z); t.w=to_tf32(b0w.w);
        *(float4*)&Bs[cB*BP + nB] = t;
        t.x=to_tf32(b1w.x); t.y=to_tf32(b1w.y); t.z=to_tf32(b1w.z); t.w=to_tf32(b1w.w);
        *(float4*)&Bs[(cB+8)*BP + nB] = t;
        __syncthreads();
        if (k0 + 16 < C) {
            a0w = *(const float4*)(WpA + k0 + 16);
            a1w = *(const float4*)(WpA + (size_t)64*C + k0 + 16);
            b0w = *(const float4*)(XpB + (size_t)(k0+16)*Npix);
            b1w = *(const float4*)(XpB + (size_t)(k0+24)*Npix);
        }
        #pragma unroll
        for (int kk = 0; kk < 2; kk++) {
            int kb = kk*8;
            uint32_t a[4][4], bb[4][2];
            #pragma unroll
            for (int mt = 0; mt < 4; mt++) {
                int m = wm + mt*16 + g;
                a[mt][0] = U(As[m*AP + kb + tg]);
                a[mt][1] = U(As[(m+8)*AP + kb + tg]);
                a[mt][2] = U(As[m*AP + kb + tg + 4]);
                a[mt][3] = U(As[(m+8)*AP + kb + tg + 4]);
            }
            #pragma unroll
            for (int nt = 0; nt < 4; nt++) {
                int n = wn + nt*8 + g;
                bb[nt][0] = U(Bs[(kb+tg)*BP + n]);
                bb[nt][1] = U(Bs[(kb+tg+4)*BP + n]);
            }
            #pragma unroll
            for (int mt = 0; mt < 4; mt++)
                #pragma unroll
                for (int nt = 0; nt < 4; nt++)
                    mma8(acc[mt][nt], a[mt], bb[nt]);
        }
        __syncthreads();
    }
    #pragma unroll
    for (int mt = 0; mt < 4; mt++) {
        int orow = o0 + wm + mt*16 + g;
        #pragma unroll
        for (int nt = 0; nt < 4; nt++) {
            int nc = n0 + wn + nt*8 + 2*tg;
            *(float2*)&Yb[(size_t)orow*Npix + nc] = make_float2(acc[mt][nt][0], acc[mt][nt][1]);
            *(float2*)&Yb[(size_t)(orow+8)*Npix + nc] = make_float2(acc[mt][nt][2], acc[mt][nt][3]);
        }
    }
}

// =================== small 64x64 conv (MPIX side, fp32) ===================
__global__ void conv1x1_small(const float* __restrict__ Wm,
                              const float* __restrict__ X,
                              float* __restrict__ Y,
                              int C, int Npix, int O) {
    __shared__ float As[16][65];
    __shared__ float Bs[16][64];
    int b = blockIdx.z;
    const float* Xb = X + (size_t)b * C * Npix;
    float* Yb = Y + (size_t)b * O * Npix;
    int o0 = blockIdx.y * 64, n0 = blockIdx.x * 64;
    int tid = threadIdx.x;
    int tx = tid & 15, ty = tid >> 4;
    float acc[4][4] = {};
    for (int k0 = 0; k0 < C; k0 += 16) {
        #pragma unroll
        for (int r = 0; r < 4; r++) {
            int idx = tid + r * 256;
            int c = idx & 15, o = idx >> 4;
            As[c][o] = Wm[(size_t)(o0 + o) * C + k0 + c];
        }
        #pragma unroll
        for (int r = 0; r < 4; r++) {
            int idx = tid + r * 256;
            int n = idx & 63, c = idx >> 6;
            Bs[c][n] = Xb[(size_t)(k0 + c) * Npix + n0 + n];
        }
        __syncthreads();
        #pragma unroll
        for (int k = 0; k < 16; k++) {
            float a[4], bb[4];
            #pragma unroll
            for (int r = 0; r < 4; r++) a[r] = As[k][ty * 4 + r];
            #pragma unroll
            for (int c2 = 0; c2 < 4; c2++) bb[c2] = Bs[k][tx * 4 + c2];
            #pragma unroll
            for (int r = 0; r < 4; r++)
                #pragma unroll
                for (int c2 = 0; c2 < 4; c2++) acc[r][c2] += a[r] * bb[c2];
        }
        __syncthreads();
    }
    #pragma unroll
    for (int r = 0; r < 4; r++)
        #pragma unroll
        for (int c2 = 0; c2 < 4; c2++)
            Yb[(size_t)(o0 + ty * 4 + r) * Npix + n0 + tx * 4 + c2] = acc[r][c2];
}

// =================== FUSED attention: 256 threads, logits retiled 32i x 64j/warp ===================
// smem (floats): Ks@0 [64][264], Vs@16896 [64][264], Ps@33792 [64][260],
//   QF@50432 [64][72] (reused [64][68]), rsw@55040 [64][4], csw@55296 [2][256],
//   csr@55808 [256]  -> total 56064 floats = 224256 B
__global__ void __launch_bounds__(256)
fused_attn(const float* __restrict__ fqv, const float* __restrict__ mqv,
           float* __restrict__ feato, float* __restrict__ dpart,
           float* __restrict__ cspart) {
    extern __shared__ float sm[];
    float* Ks  = sm;
    float* Vs  = sm + 16896;
    float* Ps  = sm + 33792;
    float* QF  = sm + 50432;
    float* rsw = sm + 55040;
    float* csw = sm + 55296;
    float* csr = sm + 55808;

    int chunk = blockIdx.x, bh = blockIdx.y;
    int b = bh >> 2, h = bh & 3;
    const float* qb  = fqv + (size_t)b * QVCH * NPIX;
    const float* fvb = qb + (size_t)CH * NPIX;
    const float* kbg = mqv + (size_t)b * QVCH * MPIX;
    const float* vbg = kbg + (size_t)CH * MPIX;

    int tid = threadIdx.x, lane = tid & 31, w = tid >> 5;
    int g = lane >> 2, tg = lane & 3;
    int wi2 = w >> 2, wj4 = w & 3;                 // logits/mapo 2x4 warp grid
    int wli = wi2 * 32, wlj = wj4 * 64;            // logits: 32i x 64j
    int wfi = (w >> 1) * 16, wfd = (w & 1) * 32;   // feato: 16i x 32d
    int wmd = wi2 * 32, wmj = wj4 * 64;            // mapo: 32d x 64j

    // CTA init: K scaled+tf32 once; V tf32
    #pragma unroll
    for (int it = 0; it < 16; it++) {
        int q4 = tid + it * 256;
        int d = q4 >> 6, j4 = (q4 & 63) << 2;
        float4 kv = *(const float4*)(kbg + (size_t)((d << 2) + h) * MPIX + j4);
        kv.x = to_tf32(kv.x * SCALE); kv.y = to_tf32(kv.y * SCALE);
        kv.z = to_tf32(kv.z * SCALE); kv.w = to_tf32(kv.w * SCALE);
        *(float4*)&Ks[d * 264 + j4] = kv;
        float4 vv = *(const float4*)(vbg + (size_t)((d << 2) + h) * MPIX + j4);
        vv.x = to_tf32(vv.x); vv.y = to_tf32(vv.y); vv.z = to_tf32(vv.z); vv.w = to_tf32(vv.w);
        *(float4*)&Vs[d * 264 + j4] = vv;
    }
    csr[tid] = 0.f;

    float acc_mo[2][8][4] = {};   // persistent 32d x 64j partial

    for (int blk = 0; blk < 8; blk++) {
        int gi0 = chunk * 512 + blk * 64;
        __syncthreads();
        // Q staged pre-truncated to tf32
        #pragma unroll
        for (int it = 0; it < 4; it++) {
            int q4 = tid + it * 256;
            int d = q4 >> 4, i4 = (q4 & 15) << 2;
            float4 qv = *(const float4*)(qb + (size_t)((d << 2) + h) * NPIX + gi0 + i4);
            qv.x = to_tf32(qv.x); qv.y = to_tf32(qv.y);
            qv.z = to_tf32(qv.z); qv.w = to_tf32(qv.w);
            *(float4*)&QF[d * 72 + i4] = qv;
        }
        __syncthreads();

        // ---- logits 1xTF32: warp 32i x 64j (2 mtiles x 8 ntiles) ----
        float accs[2][8][4] = {};
        #pragma unroll
        for (int kb8 = 0; kb8 < 64; kb8 += 8) {
            uint32_t a[2][4];
            #pragma unroll
            for (int mt = 0; mt < 2; mt++) {
                int m = wli + mt * 16;
                a[mt][0] = U(QF[(kb8 + tg) * 72 + m + g]);
                a[mt][1] = U(QF[(kb8 + tg) * 72 + m + g + 8]);
                a[mt][2] = U(QF[(kb8 + tg + 4) * 72 + m + g]);
                a[mt][3] = U(QF[(kb8 + tg + 4) * 72 + m + g + 8]);
            }
            #pragma unroll
            for (int nt = 0; nt < 8; nt++) {
                int n = wlj + nt * 8 + g;
                uint32_t bb[2] = {U(Ks[(kb8 + tg) * 264 + n]), U(Ks[(kb8 + tg + 4) * 264 + n])};
                mma8(accs[0][nt], a[0], bb);
                mma8(accs[1][nt], a[1], bb);
            }
        }

        // ---- exp + row partials (64 j per warp) + col partials (32 i per warp) ----
        float rs[2][2] = {};
        float cs0[8], cs1[8];
        #pragma unroll
        for (int nt = 0; nt < 8; nt++) { cs0[nt] = 0.f; cs1[nt] = 0.f; }
        #pragma unroll
        for (int mt = 0; mt < 2; mt++)
            #pragma unroll
            for (int nt = 0; nt < 8; nt++) {
                float e0 = __expf(accs[mt][nt][0]);
                float e1 = __expf(accs[mt][nt][1]);
                float e2 = __expf(accs[mt][nt][2]);
                float e3 = __expf(accs[mt][nt][3]);
                accs[mt][nt][0] = e0; accs[mt][nt][1] = e1;
                accs[mt][nt][2] = e2; accs[mt][nt][3] = e3;
                rs[mt][0] += e0 + e1;
                rs[mt][1] += e2 + e3;
                cs0[nt] += e0 + e2;
                cs1[nt] += e1 + e3;
            }
        #pragma unroll
        for (int off = 1; off <= 2; off <<= 1) {
            #pragma unroll
            for (int mt = 0; mt < 2; mt++) {
                rs[mt][0] += __shfl_xor_sync(0xffffffffu, rs[mt][0], off);
                rs[mt][1] += __shfl_xor_sync(0xffffffffu, rs[mt][1], off);
            }
        }
        if (tg == 0) {
            #pragma unroll
            for (int mt = 0; mt < 2; mt++) {
                rsw[(wli + mt * 16 + g) * 4 + wj4] = rs[mt][0];
                rsw[(wli + mt * 16 + g + 8) * 4 + wj4] = rs[mt][1];
            }
        }
        #pragma unroll
        for (int off = 4; off <= 16; off <<= 1) {
            #pragma unroll
            for (int nt = 0; nt < 8; nt++) {
                cs0[nt] += __shfl_xor_sync(0xffffffffu, cs0[nt], off);
                cs1[nt] += __shfl_xor_sync(0xffffffffu, cs1[nt], off);
            }
        }
        #pragma unroll
        for (int nt = 0; nt < 8; nt++) {
            if (g == nt) {
                csw[wi2 * 256 + wlj + nt * 8 + tg * 2]     = cs0[nt];
                csw[wi2 * 256 + wlj + nt * 8 + tg * 2 + 1] = cs1[nt];
            }
        }
        __syncthreads();

        csr[tid] += csw[tid] + csw[256 + tid];
        float inv[2][2];
        #pragma unroll
        for (int mt = 0; mt < 2; mt++) {
            int r0 = wli + mt * 16 + g;
            inv[mt][0] = 1.f / (rsw[r0 * 4] + rsw[r0 * 4 + 1] + rsw[r0 * 4 + 2] + rsw[r0 * 4 + 3]);
            inv[mt][1] = 1.f / (rsw[(r0 + 8) * 4] + rsw[(r0 + 8) * 4 + 1] +
                                rsw[(r0 + 8) * 4 + 2] + rsw[(r0 + 8) * 4 + 3]);
        }
        #pragma unroll
        for (int mt = 0; mt < 2; mt++)
            #pragma unroll
            for (int nt = 0; nt < 8; nt++) {
                int row = wli + mt * 16 + g;
                int col = wlj + nt * 8 + 2 * tg;
                Ps[row * 260 + col]         = to_tf32(accs[mt][nt][0] * inv[mt][0]);
                Ps[row * 260 + col + 1]     = to_tf32(accs[mt][nt][1] * inv[mt][0]);
                Ps[(row + 8) * 260 + col]     = to_tf32(accs[mt][nt][2] * inv[mt][1]);
                Ps[(row + 8) * 260 + col + 1] = to_tf32(accs[mt][nt][3] * inv[mt][1]);
            }
        __syncthreads();

        // ---- feato: O = P @ V^T (warp 16i x 32d, K=256) ----
        float acco[4][4] = {};
        #pragma unroll 4
        for (int k0 = 0; k0 < 256; k0 += 8) {
            uint32_t a[4];
            a[0] = U(Ps[(wfi + g) * 260 + k0 + tg]);
            a[1] = U(Ps[(wfi + g + 8) * 260 + k0 + tg]);
            a[2] = U(Ps[(wfi + g) * 260 + k0 + tg + 4]);
            a[3] = U(Ps[(wfi + g + 8) * 260 + k0 + tg + 4]);
            #pragma unroll
            for (int nt = 0; nt < 4; nt++) {
                int n = wfd + nt * 8 + g;
                uint32_t bb[2] = {U(Vs[n * 264 + k0 + tg]), U(Vs[n * 264 + k0 + tg + 4])};
                mma8(acco[nt], a, bb);
            }
        }
        // ---- fv * rowsum -> QF as A-tile [d 64][i 68] tf32 ----
        #pragma unroll
        for (int it = 0; it < 16; it++) {
            int idx = tid + it * 256;
            int i = idx & 63, d = idx >> 6;
            float rsv = rsw[i * 4] + rsw[i * 4 + 1] + rsw[i * 4 + 2] + rsw[i * 4 + 3];
            QF[d * 68 + i] = to_tf32(fvb[(size_t)((d << 2) + h) * NPIX + gi0 + i] * rsv);
        }
        __syncthreads();

        // ---- mapo: D += fv' @ P (warp 32d x 64j, K=64) ----
        #pragma unroll
        for (int kb = 0; kb < 64; kb += 8) {
            uint32_t am[2][4];
            #pragma unroll
            for (int mt = 0; mt < 2; mt++) {
                int m = wmd + mt * 16 + g;
                am[mt][0] = U(QF[m * 68 + kb + tg]);
                am[mt][1] = U(QF[(m + 8) * 68 + kb + tg]);
                am[mt][2] = U(QF[m * 68 + kb + tg + 4]);
                am[mt][3] = U(QF[(m + 8) * 68 + kb + tg + 4]);
            }
            #pragma unroll
            for (int nt = 0; nt < 8; nt++) {
                int n = wmj + nt * 8 + g;
                uint32_t bb[2] = {U(Ps[(kb + tg) * 260 + n]), U(Ps[(kb + tg + 4) * 260 + n])};
                mma8(acc_mo[0][nt], am[0], bb);
                mma8(acc_mo[1][nt], am[1], bb);
            }
        }
        __syncthreads();

        // ---- O staging (reuse Ps as [i 64][d 65]) + coalesced store ----
        float* OS = Ps;
        #pragma unroll
        for (int nt = 0; nt < 4; nt++) {
            int dc = wfd + nt * 8 + 2 * tg;
            OS[(wfi + g) * 65 + dc]         = acco[nt][0];
            OS[(wfi + g) * 65 + dc + 1]     = acco[nt][1];
            OS[(wfi + g + 8) * 65 + dc]     = acco[nt][2];
            OS[(wfi + g + 8) * 65 + dc + 1] = acco[nt][3];
        }
        __syncthreads();
        float* fb = feato + (size_t)b * CH * NPIX;
        #pragma unroll
        for (int it = 0; it < 16; it++) {
            int idx = tid + it * 256;
            int i = idx & 63, d = idx >> 6;
            fb[(size_t)((d << 2) + h) * NPIX + gi0 + i] = OS[i * 65 + d];
        }
    }

    // ---- CTA epilogue: D partial [d 64][j 260] in Ps, write + cs ----
    __syncthreads();
    float* St = Ps;
    #pragma unroll
    for (int mt = 0; mt < 2; mt++) {
        int d0 = wmd + mt * 16 + g;
        #pragma unroll
        for (int nt = 0; nt < 8; nt++) {
            int jc = wmj + nt * 8 + 2 * tg;
            St[d0 * 260 + jc]           = acc_mo[mt][nt][0];
            St[d0 * 260 + jc + 1]       = acc_mo[mt][nt][1];
            St[(d0 + 8) * 260 + jc]     = acc_mo[mt][nt][2];
            St[(d0 + 8) * 260 + jc + 1] = acc_mo[mt][nt][3];
        }
    }
    __syncthreads();
    float* dp = dpart + ((size_t)chunk * NBH + bh) * (64 * 256);
    #pragma unroll
    for (int it = 0; it < 16; it++) {
        int q4 = tid + it * 256;
        int d = q4 >> 6, j4 = (q4 & 63) << 2;
        *(float4*)&dp[d * 256 + j4] = make_float4(St[d * 260 + j4], St[d * 260 + j4 + 1],
                                                  St[d * 260 + j4 + 2], St[d * 260 + j4 + 3]);
    }
    cspart[((size_t)chunk * NBH + bh) * 256 + tid] = csr[tid];
}

// =================== mapo finalize (1024 blocks) ===================
__global__ void mapo_finalize(const float* __restrict__ dpart,
                              const float* __restrict__ cspart,
                              float* __restrict__ mapo) {
    int bh = blockIdx.x; int b = bh >> 2, h = bh & 3;
    int d = blockIdx.y;
    int j = threadIdx.x;
    float s = 0.f;
    #pragma unroll
    for (int ch = 0; ch < NCHUNK; ch++)
        s += cspart[((size_t)ch * NBH + bh) * 256 + j];
    float acc = 0.f;
    #pragma unroll
    for (int ch = 0; ch < NCHUNK; ch++)
        acc += dpart[((size_t)ch * NBH + bh) * (64 * 256) + d * 256 + j];
    mapo[(size_t)b * CH * MPIX + (size_t)((d << 2) + h) * MPIX + j] = acc / s;
}

// ---------------- host launch ----------------
extern "C" void kernel_launch(void* const* d_in, const int* in_sizes, int n_in,
                              void* d_out, int out_size) {
    const float* feat = (const float*)d_in[0];
    const float* smap = (const float*)d_in[1];
    const float* Wfqv = (const float*)d_in[2];
    const float* Wmqv = (const float*)d_in[3];
    const float* Wfo  = (const float*)d_in[4];
    const float* Wmo  = (const float*)d_in[5];
    float* out = (float*)d_out;
    float* feat_out = out;
    float* map_out  = out + (size_t)BATCH * CH * NPIX;

    float *p_fqv, *p_mqv, *p_feato, *p_mapo, *p_dpart, *p_cspart;
    cudaGetSymbolAddress((void**)&p_fqv, g_fqv);
    cudaGetSymbolAddress((void**)&p_mqv, g_mqv);
    cudaGetSymbolAddress((void**)&p_feato, g_feato);
    cudaGetSymbolAddress((void**)&p_mapo, g_mapo);
    cudaGetSymbolAddress((void**)&p_dpart, g_dpart);
    cudaGetSymbolAddress((void**)&p_cspart, g_cspart);

    const int fused_smem = 56064 * 4;   // 224256 B
    cudaFuncSetAttribute(fused_attn, cudaFuncAttributeMaxDynamicSharedMemorySize, fused_smem);

    // 1) QV projections
    conv_tf32<<<dim3(NPIX / 128, QVCH / 128, BATCH), 256>>>(Wfqv, feat, p_fqv, CH, NPIX, QVCH);
    conv1x1_small<<<dim3(MPIX / 64, QVCH / 64, BATCH), 256>>>(Wmqv, smap, p_mqv, CH, MPIX, QVCH);

    // marker so fused_attn is the 4th launch (profiled by ncu)
    prof_marker<<<1, 32>>>();

    // 2) fused attention (256 threads, retiled logits)
    fused_attn<<<dim3(NCHUNK, NBH), 256, fused_smem>>>(p_fqv, p_mqv, p_feato, p_dpart, p_cspart);

    // 3) map_o finalize
    mapo_finalize<<<dim3(NBH, 64), 256>>>(p_dpart, p_cspart, p_mapo);

    // 4) output projections
    conv_tf32<<<dim3(NPIX / 128, CH / 128, BATCH), 256>>>(Wfo, p_feato, feat_out, CH, NPIX, CH);
    conv1x1_small<<<dim3(MPIX / 64, CH / 64, BATCH), 256>>>(Wmo, p_mapo, map_out, CH, MPIX, CH);
}